// round 10
// baseline (speedup 1.0000x reference)
#include <cuda_runtime.h>
#include <cuda_fp16.h>

// ---------------------------------------------------------------------------
// out[m,n] = sum_r sum_k A[r,m,k] * W[r,n,k]   (M=N=4096, K=8*1024)
// fp32 in/out, fp16 single-pass mma.sync.m16n8k16 (f32 accumulate).
// R10: CTA 128x256, 8 warps of 64x64 (was 128x128 / 64x32) to cut l1tex
// bytes per unit work ~1.45x (the R9 profile is L1-bandwidth-bound at 82%).
// Quarter-chunk staging keeps <=48 staging regs in flight; fragments
// single-buffered; producer ops fill the ldsm->mma latency window.
// ---------------------------------------------------------------------------

using u32 = unsigned int;

static constexpr int NT      = 4096;   // N total (also M total)
static constexpr int KL      = 1024;   // K per rank slab
static constexpr int NCHUNK  = 128;    // 8192 / 64
static constexpr int R_B     = 16384;  // B region offset within a stage (A fp16 = 16KB)
static constexpr int STAGE   = 49152;  // A 16KB + B 32KB
static constexpr int SMEM_TOTAL = 2 * STAGE;   // 96 KB

static __device__ __forceinline__ u32 smem_u32(const void* p) {
    u32 a;
    asm("{ .reg .u64 t; cvta.to.shared.u64 t, %1; cvt.u32.u64 %0, t; }"
        : "=r"(a) : "l"(p));
    return a;
}

static __device__ __forceinline__ void ldsm4(u32 addr, u32* r) {
    asm volatile("ldmatrix.sync.aligned.m8n8.x4.shared.b16 {%0,%1,%2,%3}, [%4];"
                 : "=r"(r[0]), "=r"(r[1]), "=r"(r[2]), "=r"(r[3]) : "r"(addr));
}

static __device__ __forceinline__ void mma16816(float* c, const u32* a,
                                                u32 b0, u32 b1) {
    asm volatile(
        "mma.sync.aligned.m16n8k16.row.col.f32.f16.f16.f32 "
        "{%0,%1,%2,%3}, {%4,%5,%6,%7}, {%8,%9}, {%0,%1,%2,%3};"
        : "+f"(c[0]), "+f"(c[1]), "+f"(c[2]), "+f"(c[3])
        : "r"(a[0]), "r"(a[1]), "r"(a[2]), "r"(a[3]), "r"(b0), "r"(b1));
}

// 8 consecutive fp32 -> 8 fp16, one 16B STS at the swizzled address.
static __device__ __forceinline__ void cvt_sts(float4 v0, float4 v1, u32 addr) {
    const __half2 p0 = __floats2half2_rn(v0.x, v0.y);
    const __half2 p1 = __floats2half2_rn(v0.z, v0.w);
    const __half2 p2 = __floats2half2_rn(v1.x, v1.y);
    const __half2 p3 = __floats2half2_rn(v1.z, v1.w);
    asm volatile("st.shared.v4.b32 [%0], {%1,%2,%3,%4};"
                 :: "r"(addr),
                    "r"(*(const u32*)&p0), "r"(*(const u32*)&p1),
                    "r"(*(const u32*)&p2), "r"(*(const u32*)&p3) : "memory");
}

__global__ __launch_bounds__(256, 1)
void gemm_rs_kernel(const float* __restrict__ A,
                    const float* __restrict__ W,
                    float* __restrict__ out)
{
    extern __shared__ char smem[];
    const u32 sb  = smem_u32(smem);
    const int tid = threadIdx.x;
    const int lane = tid & 31;
    const int w    = tid >> 5;

    // CTA raster: groups of 8 M-tiles x 16 N-tiles
    const int lin = blockIdx.x;
    const int grp = lin >> 7;
    const int rem = lin & 127;
    const int m0  = ((grp << 3) + (rem & 7)) << 7;   // * 128
    const int n0  = (rem >> 3) << 8;                 // * 256

    // ---- staging thread map: tRow = row, tK = pair-half within quarter ----
    const int tRow = tid >> 1;                 // 0..127
    const int tK   = tid & 1;

    // ---- ldmatrix per-lane bases: warp grid 2(M) x 4(N), tile 64x64 ----
    const int wm = (w >> 2) << 6;              // 0 or 64
    const int wn = (w & 3) << 6;               // 0,64,128,192
    const u32 raA = (u32)(wm + (lane & 15)) * 128;
    const u32 raB = (u32)(wn + (lane & 15)) * 128 + R_B;
    const u32 khalf = (u32)(lane >> 4);
    const u32 l7    = (u32)(lane & 7);

    float c[4][8][4] = {};
    u32 ah[4][4], bh[4][4];

    // Quarter staging: one A pair + two B pairs per thread per quarter.
    float4 qa[2][2];
    float4 qb[2][2][2];

    // LDG quarter q (k-span of 16 fp32) of chunk ic into slot s.
    auto ldg_q = [&](int ic, int q, int s) {
        const int r = ic >> 4;
        const size_t base = (size_t)r * ((size_t)NT * KL)
                          + (size_t)((ic & 15) << 6)
                          + (size_t)(q * 16 + tK * 8);
        const float* pa = A + (size_t)(m0 + tRow) * KL + base;
        qa[s][0] = *reinterpret_cast<const float4*>(pa);
        qa[s][1] = *reinterpret_cast<const float4*>(pa + 4);
        #pragma unroll
        for (int i = 0; i < 2; ++i) {
            const float* pb = W + (size_t)(n0 + tRow + i * 128) * KL + base;
            qb[s][i][0] = *reinterpret_cast<const float4*>(pb);
            qb[s][i][1] = *reinterpret_cast<const float4*>(pb + 4);
        }
    };

    // STS quarter q from slot s into stage buffer buf.
    auto sts_q = [&](int buf, int q, int s) {
        const u32 base = sb + (u32)buf * STAGE;
        const u32 kchunk = (u32)(q * 2 + tK);          // 16B chunk in 128B row
        const u32 swzA = (kchunk ^ ((u32)tRow & 7)) << 4;
        cvt_sts(qa[s][0], qa[s][1], base + (u32)tRow * 128 + swzA);
        #pragma unroll
        for (int i = 0; i < 2; ++i) {
            const u32 row = (u32)(tRow + i * 128);
            const u32 swz = (kchunk ^ (row & 7)) << 4;
            cvt_sts(qb[s][i][0], qb[s][i][1], base + R_B + row * 128 + swz);
        }
    };

    auto ldsm_kk = [&](u32 base, int kk) {
        const u32 off = (((u32)(2 * kk) + khalf) ^ l7) << 4;
        const u32 pa = base + raA + off;
        const u32 pb = base + raB + off;
        #pragma unroll
        for (int t = 0; t < 4; ++t) ldsm4(pa + (u32)t * 2048, ah[t]);
        #pragma unroll
        for (int t = 0; t < 4; ++t) ldsm4(pb + (u32)t * 2048, bh[t]);
    };

    // ---- prologue: stage chunk 0 into buffer 0 ----
    ldg_q(0, 0, 0); ldg_q(0, 1, 1);
    sts_q(0, 0, 0); sts_q(0, 1, 1);
    ldg_q(0, 2, 0); ldg_q(0, 3, 1);
    sts_q(0, 2, 0); sts_q(0, 3, 1);
    __syncthreads();

    #pragma unroll 1
    for (int ic = 0; ic < NCHUNK; ++ic) {
        const u32 base = sb + (u32)(ic & 1) * STAGE;
        const int  nb  = (ic + 1) & 1;
        const bool hn  = (ic + 1 < NCHUNK);

        #pragma unroll
        for (int kk = 0; kk < 4; ++kk) {
            ldsm_kk(base, kk);

            // Producer ops fill the ldsm->mma latency window; staging regs
            // for the next chunk's quarters: <=2 slots (48 regs) in flight.
            if (kk == 0)      { if (hn) { ldg_q(ic + 1, 0, 0); ldg_q(ic + 1, 1, 1); } }
            else if (kk == 1) { if (hn) { sts_q(nb, 0, 0);     ldg_q(ic + 1, 2, 0); } }
            else if (kk == 2) { if (hn) { sts_q(nb, 1, 1);     ldg_q(ic + 1, 3, 1); } }
            else              { if (hn) { sts_q(nb, 2, 0);     sts_q(nb, 3, 1);     } }

            // mt -> j: same-accumulator dep distance = 32 MMAs
            #pragma unroll
            for (int mt = 0; mt < 4; ++mt) {
                #pragma unroll
                for (int j = 0; j < 8; ++j) {
                    const int nt = j >> 1, s = j & 1;
                    mma16816(c[mt][j], ah[mt], bh[nt][s], bh[nt][s + 2]);
                }
            }
        }
        __syncthreads();
    }

    // ---- epilogue ----
    const int orow = m0 + wm + (lane >> 2);
    const int ocol = n0 + wn + ((lane & 3) << 1);
    #pragma unroll
    for (int mt = 0; mt < 4; ++mt) {
        #pragma unroll
        for (int j = 0; j < 8; ++j) {
            float* p = out + (size_t)(orow + mt * 16) * NT + (ocol + j * 8);
            *reinterpret_cast<float2*>(p) = make_float2(c[mt][j][0], c[mt][j][1]);
            *reinterpret_cast<float2*>(p + (size_t)8 * NT) =
                make_float2(c[mt][j][2], c[mt][j][3]);
        }
    }
}

extern "C" void kernel_launch(void* const* d_in, const int* in_sizes, int n_in,
                              void* d_out, int out_size)
{
    const float* A = (const float*)d_in[0];   // [8, 4096, 1024]
    const float* W = (const float*)d_in[1];   // [8, 4096, 1024]
    float* out = (float*)d_out;               // [8, 512, 4096] == [4096, 4096]

    cudaFuncSetAttribute(gemm_rs_kernel,
                         cudaFuncAttributeMaxDynamicSharedMemorySize, SMEM_TOTAL);
    gemm_rs_kernel<<<512, 256, SMEM_TOTAL>>>(A, W, out);
}

// round 11
// speedup vs baseline: 1.3614x; 1.3614x over previous
#include <cuda_runtime.h>
#include <cuda_fp16.h>

// ---------------------------------------------------------------------------
// out[m,n] = sum_r sum_k A[r,m,k] * W[r,n,k]   (M=N=4096, K=8*1024)
// fp32 in/out, fp16 single-pass mma.sync.m16n8k16 (f32 accumulate).
// R11: (1) one-time fp32->fp16 convert pass into __device__ scratch;
// (2) GEMM stages fp16 tiles with cp.async.cg (L1-bypassing, no RF staging,
// no cvt in the hot loop) in a 4-stage ring. Compute loop identical to the
// proven R9 shape: CTA 128x128, 8 warps of 64x32, K-chunk 64, fragment
// double-buffering over K16 blocks.
// ---------------------------------------------------------------------------

using u32 = unsigned int;

static constexpr int NT      = 4096;       // N total (also M total)
static constexpr int KL      = 1024;       // K per rank slab
static constexpr int NCHUNK  = 128;        // 8192 / 64
static constexpr int R_B     = 16384;      // B region offset within a stage
static constexpr int STAGE   = 32768;      // A 16KB + B 16KB (fp16)
static constexpr int NSTG    = 4;
static constexpr int SMEM_TOTAL = NSTG * STAGE;          // 128 KB
static constexpr size_t NA   = (size_t)8 * NT * KL;      // elems per tensor

// fp16 scratch: A at [0, NA), W at [NA, 2*NA)  (128 MB)
__device__ __half g_fp16[2 * NA];

// ---------------- convert pass ----------------
__global__ __launch_bounds__(256) void cvt_kernel(const float* __restrict__ A,
                                                  const float* __restrict__ W)
{
    const size_t total8 = (2 * NA) / 8;
    const size_t stride = (size_t)gridDim.x * blockDim.x;
    for (size_t g = (size_t)blockIdx.x * blockDim.x + threadIdx.x;
         g < total8; g += stride) {
        const size_t off = g * 8;
        const float* src = (off < NA) ? (A + off) : (W + (off - NA));
        const float4 v0 = *reinterpret_cast<const float4*>(src);
        const float4 v1 = *reinterpret_cast<const float4*>(src + 4);
        const __half2 h0 = __floats2half2_rn(v0.x, v0.y);
        const __half2 h1 = __floats2half2_rn(v0.z, v0.w);
        const __half2 h2 = __floats2half2_rn(v1.x, v1.y);
        const __half2 h3 = __floats2half2_rn(v1.z, v1.w);
        uint4 pk;
        pk.x = *(const u32*)&h0; pk.y = *(const u32*)&h1;
        pk.z = *(const u32*)&h2; pk.w = *(const u32*)&h3;
        *reinterpret_cast<uint4*>(&g_fp16[off]) = pk;
    }
}

// ---------------- GEMM ----------------
static __device__ __forceinline__ u32 smem_u32(const void* p) {
    u32 a;
    asm("{ .reg .u64 t; cvta.to.shared.u64 t, %1; cvt.u32.u64 %0, t; }"
        : "=r"(a) : "l"(p));
    return a;
}

static __device__ __forceinline__ void ldsm4(u32 addr, u32* r) {
    asm volatile("ldmatrix.sync.aligned.m8n8.x4.shared.b16 {%0,%1,%2,%3}, [%4];"
                 : "=r"(r[0]), "=r"(r[1]), "=r"(r[2]), "=r"(r[3]) : "r"(addr));
}

static __device__ __forceinline__ void mma16816(float* c, const u32* a,
                                                u32 b0, u32 b1) {
    asm volatile(
        "mma.sync.aligned.m16n8k16.row.col.f32.f16.f16.f32 "
        "{%0,%1,%2,%3}, {%4,%5,%6,%7}, {%8,%9}, {%0,%1,%2,%3};"
        : "+f"(c[0]), "+f"(c[1]), "+f"(c[2]), "+f"(c[3])
        : "r"(a[0]), "r"(a[1]), "r"(a[2]), "r"(a[3]), "r"(b0), "r"(b1));
}

static __device__ __forceinline__ void cp16(u32 sdst, const void* gsrc) {
    asm volatile("cp.async.cg.shared.global [%0], [%1], 16;"
                 :: "r"(sdst), "l"(gsrc) : "memory");
}

__global__ __launch_bounds__(256, 1)
void gemm_rs_kernel(float* __restrict__ out)
{
    extern __shared__ char smem[];
    const u32 sb  = smem_u32(smem);
    const int tid = threadIdx.x;
    const int lane = tid & 31;
    const int w    = tid >> 5;

    // CTA raster: groups of 8 M-tiles x 32 N-tiles (wave working set ~ L2)
    const int lin = blockIdx.x;
    const int grp = lin >> 8;
    const int rem = lin & 255;
    const int m0  = ((grp << 3) + (rem & 7)) << 7;   // * 128
    const int n0  = (rem >> 3) << 7;

    // ---- cp.async thread map: row = tid>>1, 4 consecutive 16B chunks ----
    const int cRow = tid >> 1;                 // 0..127
    const int jb   = (tid & 1) << 2;           // 0 or 4 (16B-chunk index)
    const __half* gA = g_fp16 + (size_t)(m0 + cRow) * KL + (size_t)jb * 8;
    const __half* gB = g_fp16 + NA + (size_t)(n0 + cRow) * KL + (size_t)jb * 8;
    const u32 sRowA = (u32)cRow * 128;
    u32 swz[4];
    #pragma unroll
    for (int j2 = 0; j2 < 4; ++j2)
        swz[j2] = (u32)(((jb + j2) ^ (cRow & 7)) << 4);

    // ---- ldmatrix per-lane bases (R9 layout) ----
    const int wm = (w >> 2) << 6;              // 0 or 64
    const int wn = (w & 3) << 5;               // 0,32,64,96
    const u32 raA = (u32)(wm + (lane & 15)) * 128;
    const u32 raB = (u32)(wn + (lane & 15)) * 128 + R_B;
    const u32 khalf = (u32)(lane >> 4);
    const u32 l7    = (u32)(lane & 7);

    float c[4][4][4] = {};
    u32 ah[2][4][4], bh[2][2][4];

    auto issue = [&](int ic) {
        if (ic < NCHUNK) {
            const u32 sdst = sb + (u32)(ic & 3) * STAGE;
            const size_t kbase = (size_t)(ic >> 4) * ((size_t)NT * KL)
                               + (size_t)((ic & 15) << 6);
            const __half* pa = gA + kbase;
            const __half* pb = gB + kbase;
            #pragma unroll
            for (int j2 = 0; j2 < 4; ++j2) {
                cp16(sdst + sRowA + swz[j2], pa + j2 * 8);
                cp16(sdst + R_B + sRowA + swz[j2], pb + j2 * 8);
            }
        }
        asm volatile("cp.async.commit_group;" ::: "memory");
    };

    auto ldsm_kk = [&](u32 base, int kk, int fb) {
        const u32 off = (((u32)(2 * kk) + khalf) ^ l7) << 4;
        const u32 pa = base + raA + off;
        const u32 pb = base + raB + off;
        #pragma unroll
        for (int t = 0; t < 4; ++t) ldsm4(pa + (u32)t * 2048, ah[fb][t]);
        #pragma unroll
        for (int t = 0; t < 2; ++t) ldsm4(pb + (u32)t * 2048, bh[fb][t]);
    };

    // ---- prologue: stage chunks 0..2 ----
    issue(0); issue(1); issue(2);

    #pragma unroll 1
    for (int ic = 0; ic < NCHUNK; ++ic) {
        const u32 base = sb + (u32)(ic & 3) * STAGE;

        // Own-group wait, then barrier: makes every thread's chunk-ic data
        // visible AND guarantees all warps are done reading buffer
        // (ic-1)%4 == (ic+3)%4 before anyone overwrites it below.
        asm volatile("cp.async.wait_group 2;" ::: "memory");
        __syncthreads();

        issue(ic + 3);

        ldsm_kk(base, 0, 0);
        #pragma unroll
        for (int kk = 0; kk < 4; ++kk) {
            const int fb = kk & 1;
            if (kk < 3) ldsm_kk(base, kk + 1, fb ^ 1);   // prefetch next block

            // mt -> j: same-accumulator dep distance = 16 MMAs
            #pragma unroll
            for (int mt = 0; mt < 4; ++mt) {
                #pragma unroll
                for (int j = 0; j < 4; ++j) {
                    const int t = j >> 1, s = j & 1;
                    mma16816(c[mt][j], ah[fb][mt], bh[fb][t][s], bh[fb][t][s + 2]);
                }
            }
        }
    }

    // ---- epilogue ----
    const int orow = m0 + wm + (lane >> 2);
    const int ocol = n0 + wn + ((lane & 3) << 1);
    #pragma unroll
    for (int mt = 0; mt < 4; ++mt) {
        #pragma unroll
        for (int j = 0; j < 4; ++j) {
            float* p = out + (size_t)(orow + mt * 16) * NT + (ocol + j * 8);
            *reinterpret_cast<float2*>(p) = make_float2(c[mt][j][0], c[mt][j][1]);
            *reinterpret_cast<float2*>(p + (size_t)8 * NT) =
                make_float2(c[mt][j][2], c[mt][j][3]);
        }
    }
}

extern "C" void kernel_launch(void* const* d_in, const int* in_sizes, int n_in,
                              void* d_out, int out_size)
{
    const float* A = (const float*)d_in[0];   // [8, 4096, 1024]
    const float* W = (const float*)d_in[1];   // [8, 4096, 1024]
    float* out = (float*)d_out;               // [8, 512, 4096] == [4096, 4096]

    cvt_kernel<<<4096, 256>>>(A, W);

    cudaFuncSetAttribute(gemm_rs_kernel,
                         cudaFuncAttributeMaxDynamicSharedMemorySize, SMEM_TOTAL);
    gemm_rs_kernel<<<1024, 256, SMEM_TOTAL>>>(out);
}

// round 12
// speedup vs baseline: 1.3704x; 1.0066x over previous
#include <cuda_runtime.h>
#include <cuda_fp16.h>

// ---------------------------------------------------------------------------
// out[m,n] = sum_r sum_k A[r,m,k] * W[r,n,k]   (M=N=4096, K=8*1024)
// fp32 in/out, fp16 single-pass mma.sync.m16n8k16 (f32 accumulate).
// R12: R11's cp.async.cg staging (no staging regs, L1-bypassing) + R10's
// CTA 128x256 / warp 64x64 compute shape (2x MMA work per barrier, better
// ldsm:MMA ratio). 4-stage ring, 48KB/stage, 192KB smem, grid 512.
// ---------------------------------------------------------------------------

using u32 = unsigned int;

static constexpr int NT      = 4096;       // N total (also M total)
static constexpr int KL      = 1024;       // K per rank slab
static constexpr int NCHUNK  = 128;        // 8192 / 64
static constexpr int R_B     = 16384;      // B region offset within a stage
static constexpr int STAGE   = 49152;      // A 16KB + B 32KB (fp16)
static constexpr int NSTG    = 4;
static constexpr int SMEM_TOTAL = NSTG * STAGE;          // 192 KB
static constexpr size_t NA   = (size_t)8 * NT * KL;      // elems per tensor

// fp16 scratch: A at [0, NA), W at [NA, 2*NA)  (128 MB)
__device__ __half g_fp16[2 * NA];

// ---------------- convert pass ----------------
__global__ __launch_bounds__(256) void cvt_kernel(const float* __restrict__ A,
                                                  const float* __restrict__ W)
{
    const size_t total8 = (2 * NA) / 8;
    const size_t stride = (size_t)gridDim.x * blockDim.x;
    for (size_t g = (size_t)blockIdx.x * blockDim.x + threadIdx.x;
         g < total8; g += stride) {
        const size_t off = g * 8;
        const float* src = (off < NA) ? (A + off) : (W + (off - NA));
        const float4 v0 = *reinterpret_cast<const float4*>(src);
        const float4 v1 = *reinterpret_cast<const float4*>(src + 4);
        const __half2 h0 = __floats2half2_rn(v0.x, v0.y);
        const __half2 h1 = __floats2half2_rn(v0.z, v0.w);
        const __half2 h2 = __floats2half2_rn(v1.x, v1.y);
        const __half2 h3 = __floats2half2_rn(v1.z, v1.w);
        uint4 pk;
        pk.x = *(const u32*)&h0; pk.y = *(const u32*)&h1;
        pk.z = *(const u32*)&h2; pk.w = *(const u32*)&h3;
        *reinterpret_cast<uint4*>(&g_fp16[off]) = pk;
    }
}

// ---------------- GEMM ----------------
static __device__ __forceinline__ u32 smem_u32(const void* p) {
    u32 a;
    asm("{ .reg .u64 t; cvta.to.shared.u64 t, %1; cvt.u32.u64 %0, t; }"
        : "=r"(a) : "l"(p));
    return a;
}

static __device__ __forceinline__ void ldsm4(u32 addr, u32* r) {
    asm volatile("ldmatrix.sync.aligned.m8n8.x4.shared.b16 {%0,%1,%2,%3}, [%4];"
                 : "=r"(r[0]), "=r"(r[1]), "=r"(r[2]), "=r"(r[3]) : "r"(addr));
}

static __device__ __forceinline__ void mma16816(float* c, const u32* a,
                                                u32 b0, u32 b1) {
    asm volatile(
        "mma.sync.aligned.m16n8k16.row.col.f32.f16.f16.f32 "
        "{%0,%1,%2,%3}, {%4,%5,%6,%7}, {%8,%9}, {%0,%1,%2,%3};"
        : "+f"(c[0]), "+f"(c[1]), "+f"(c[2]), "+f"(c[3])
        : "r"(a[0]), "r"(a[1]), "r"(a[2]), "r"(a[3]), "r"(b0), "r"(b1));
}

static __device__ __forceinline__ void cp16(u32 sdst, const void* gsrc) {
    asm volatile("cp.async.cg.shared.global [%0], [%1], 16;"
                 :: "r"(sdst), "l"(gsrc) : "memory");
}

__global__ __launch_bounds__(256, 1)
void gemm_rs_kernel(float* __restrict__ out)
{
    extern __shared__ char smem[];
    const u32 sb  = smem_u32(smem);
    const int tid = threadIdx.x;
    const int lane = tid & 31;
    const int w    = tid >> 5;

    // CTA raster: groups of 8 M-tiles x 16 N-tiles (wave working set ~ L2)
    const int lin = blockIdx.x;
    const int grp = lin >> 7;
    const int rem = lin & 127;
    const int m0  = ((grp << 3) + (rem & 7)) << 7;   // * 128
    const int n0  = (rem >> 3) << 8;                 // * 256

    // ---- cp.async thread map: row = tid>>1, 4 consecutive 16B chunks ----
    const int cRow = tid >> 1;                 // 0..127
    const int jb   = (tid & 1) << 2;           // 0 or 4 (16B-chunk index)
    const __half* gA = g_fp16 + (size_t)(m0 + cRow) * KL + (size_t)jb * 8;
    const __half* gB = g_fp16 + NA + (size_t)(n0 + cRow) * KL + (size_t)jb * 8;
    const u32 sRow = (u32)cRow * 128;
    u32 swz[4];
    #pragma unroll
    for (int j2 = 0; j2 < 4; ++j2)
        swz[j2] = (u32)(((jb + j2) ^ (cRow & 7)) << 4);

    // ---- ldmatrix per-lane bases: warp grid 2(M) x 4(N), tile 64x64 ----
    const int wm = (w >> 2) << 6;              // 0 or 64
    const int wn = (w & 3) << 6;               // 0,64,128,192
    const u32 raA = (u32)(wm + (lane & 15)) * 128;
    const u32 raB = (u32)(wn + (lane & 15)) * 128 + R_B;
    const u32 khalf = (u32)(lane >> 4);
    const u32 l7    = (u32)(lane & 7);

    float c[4][8][4] = {};
    u32 ah[2][4][4], bh[2][4][4];

    auto issue = [&](int ic) {
        if (ic < NCHUNK) {
            const u32 sdst = sb + (u32)(ic & 3) * STAGE;
            const size_t kbase = (size_t)(ic >> 4) * ((size_t)NT * KL)
                               + (size_t)((ic & 15) << 6);
            const __half* pa = gA + kbase;
            const __half* pb = gB + kbase;
            #pragma unroll
            for (int j2 = 0; j2 < 4; ++j2)
                cp16(sdst + sRow + swz[j2], pa + j2 * 8);
            #pragma unroll
            for (int i = 0; i < 2; ++i) {
                const u32 brow = sdst + R_B + sRow + (u32)i * 16384;
                const __half* pbi = pb + (size_t)i * 128 * KL;
                #pragma unroll
                for (int j2 = 0; j2 < 4; ++j2)
                    cp16(brow + swz[j2], pbi + j2 * 8);
            }
        }
        asm volatile("cp.async.commit_group;" ::: "memory");
    };

    auto ldsm_kk = [&](u32 base, int kk, int fb) {
        const u32 off = (((u32)(2 * kk) + khalf) ^ l7) << 4;
        const u32 pa = base + raA + off;
        const u32 pb = base + raB + off;
        #pragma unroll
        for (int t = 0; t < 4; ++t) ldsm4(pa + (u32)t * 2048, ah[fb][t]);
        #pragma unroll
        for (int t = 0; t < 4; ++t) ldsm4(pb + (u32)t * 2048, bh[fb][t]);
    };

    // ---- prologue: stage chunks 0..2 ----
    issue(0); issue(1); issue(2);

    #pragma unroll 1
    for (int ic = 0; ic < NCHUNK; ++ic) {
        const u32 base = sb + (u32)(ic & 3) * STAGE;

        // Own-group wait, then barrier: chunk-ic data visible to all warps
        // AND all warps done reading the buffer issue() below overwrites.
        asm volatile("cp.async.wait_group 2;" ::: "memory");
        __syncthreads();

        issue(ic + 3);

        ldsm_kk(base, 0, 0);
        #pragma unroll
        for (int kk = 0; kk < 4; ++kk) {
            const int fb = kk & 1;
            if (kk < 3) ldsm_kk(base, kk + 1, fb ^ 1);   // prefetch next block

            // mt -> j: same-accumulator dep distance = 32 MMAs
            #pragma unroll
            for (int mt = 0; mt < 4; ++mt) {
                #pragma unroll
                for (int j = 0; j < 8; ++j) {
                    const int nt = j >> 1, s = j & 1;
                    mma16816(c[mt][j], ah[fb][mt], bh[fb][nt][s], bh[fb][nt][s + 2]);
                }
            }
        }
    }

    // ---- epilogue ----
    const int orow = m0 + wm + (lane >> 2);
    const int ocol = n0 + wn + ((lane & 3) << 1);
    #pragma unroll
    for (int mt = 0; mt < 4; ++mt) {
        #pragma unroll
        for (int j = 0; j < 8; ++j) {
            float* p = out + (size_t)(orow + mt * 16) * NT + (ocol + j * 8);
            *reinterpret_cast<float2*>(p) = make_float2(c[mt][j][0], c[mt][j][1]);
            *reinterpret_cast<float2*>(p + (size_t)8 * NT) =
                make_float2(c[mt][j][2], c[mt][j][3]);
        }
    }
}

extern "C" void kernel_launch(void* const* d_in, const int* in_sizes, int n_in,
                              void* d_out, int out_size)
{
    const float* A = (const float*)d_in[0];   // [8, 4096, 1024]
    const float* W = (const float*)d_in[1];   // [8, 4096, 1024]
    float* out = (float*)d_out;               // [8, 512, 4096] == [4096, 4096]

    cvt_kernel<<<4096, 256>>>(A, W);

    cudaFuncSetAttribute(gemm_rs_kernel,
                         cudaFuncAttributeMaxDynamicSharedMemorySize, SMEM_TOTAL);
    gemm_rs_kernel<<<512, 256, SMEM_TOTAL>>>(out);
}

// round 13
// speedup vs baseline: 1.4055x; 1.0256x over previous
#include <cuda_runtime.h>
#include <cuda_fp16.h>

// ---------------------------------------------------------------------------
// out[m,n] = sum_r sum_k A[r,m,k] * W[r,n,k]   (M=N=4096, K=8*1024)
// fp32 in/out, fp16 single-pass mma.sync.m16n8k16 (f32 accumulate).
// R13: occupancy attack. R11's proven per-warp shape (64x32, ~116 regs) but
// 16 warps / 512 threads per CTA -> 4 warps/SMSP latency hiding (was 2).
// CTA 256x128, 4-stage cp.async.cg ring (48KB/stage, 192KB smem), one-time
// fp32->fp16 convert pass into __device__ scratch.
// ---------------------------------------------------------------------------

using u32 = unsigned int;

static constexpr int NT      = 4096;       // N total (also M total)
static constexpr int KL      = 1024;       // K per rank slab
static constexpr int NCHUNK  = 128;        // 8192 / 64
static constexpr int R_B     = 32768;      // B region offset within a stage
static constexpr int STAGE   = 49152;      // A 32KB + B 16KB (fp16)
static constexpr int NSTG    = 4;
static constexpr int SMEM_TOTAL = NSTG * STAGE;          // 192 KB
static constexpr size_t NA   = (size_t)8 * NT * KL;      // elems per tensor

// fp16 scratch: A at [0, NA), W at [NA, 2*NA)  (128 MB)
__device__ __half g_fp16[2 * NA];

// ---------------- convert pass ----------------
__global__ __launch_bounds__(256) void cvt_kernel(const float* __restrict__ A,
                                                  const float* __restrict__ W)
{
    const size_t total8 = (2 * NA) / 8;
    const size_t stride = (size_t)gridDim.x * blockDim.x;
    for (size_t g = (size_t)blockIdx.x * blockDim.x + threadIdx.x;
         g < total8; g += stride) {
        const size_t off = g * 8;
        const float* src = (off < NA) ? (A + off) : (W + (off - NA));
        const float4 v0 = *reinterpret_cast<const float4*>(src);
        const float4 v1 = *reinterpret_cast<const float4*>(src + 4);
        const __half2 h0 = __floats2half2_rn(v0.x, v0.y);
        const __half2 h1 = __floats2half2_rn(v0.z, v0.w);
        const __half2 h2 = __floats2half2_rn(v1.x, v1.y);
        const __half2 h3 = __floats2half2_rn(v1.z, v1.w);
        uint4 pk;
        pk.x = *(const u32*)&h0; pk.y = *(const u32*)&h1;
        pk.z = *(const u32*)&h2; pk.w = *(const u32*)&h3;
        *reinterpret_cast<uint4*>(&g_fp16[off]) = pk;
    }
}

// ---------------- GEMM ----------------
static __device__ __forceinline__ u32 smem_u32(const void* p) {
    u32 a;
    asm("{ .reg .u64 t; cvta.to.shared.u64 t, %1; cvt.u32.u64 %0, t; }"
        : "=r"(a) : "l"(p));
    return a;
}

static __device__ __forceinline__ void ldsm4(u32 addr, u32* r) {
    asm volatile("ldmatrix.sync.aligned.m8n8.x4.shared.b16 {%0,%1,%2,%3}, [%4];"
                 : "=r"(r[0]), "=r"(r[1]), "=r"(r[2]), "=r"(r[3]) : "r"(addr));
}

static __device__ __forceinline__ void mma16816(float* c, const u32* a,
                                                u32 b0, u32 b1) {
    asm volatile(
        "mma.sync.aligned.m16n8k16.row.col.f32.f16.f16.f32 "
        "{%0,%1,%2,%3}, {%4,%5,%6,%7}, {%8,%9}, {%0,%1,%2,%3};"
        : "+f"(c[0]), "+f"(c[1]), "+f"(c[2]), "+f"(c[3])
        : "r"(a[0]), "r"(a[1]), "r"(a[2]), "r"(a[3]), "r"(b0), "r"(b1));
}

static __device__ __forceinline__ void cp16(u32 sdst, const void* gsrc) {
    asm volatile("cp.async.cg.shared.global [%0], [%1], 16;"
                 :: "r"(sdst), "l"(gsrc) : "memory");
}

__global__ __launch_bounds__(512, 1)
void gemm_rs_kernel(float* __restrict__ out)
{
    extern __shared__ char smem[];
    const u32 sb  = smem_u32(smem);
    const int tid = threadIdx.x;
    const int lane = tid & 31;
    const int w    = tid >> 5;

    // CTA grid: 16 M-tiles (256) x 32 N-tiles (128) = 512 CTAs.
    // Raster: groups of 8 M-tiles x 32 N-tiles (wave working set ~70MB < L2).
    const int lin = blockIdx.x;
    const int grp = lin >> 8;                  // 0..1
    const int rem = lin & 255;
    const int m0  = ((grp << 3) + (rem & 7)) << 8;   // * 256
    const int n0  = (rem >> 3) << 7;                 // * 128

    // ---- cp.async thread maps ----
    // A: 256 rows x 8 chunks(16B) -> 4 chunks per thread
    const int aRow = tid >> 1;                 // 0..255
    const int ajb  = (tid & 1) << 2;           // 0 or 4
    // B: 128 rows x 8 chunks -> 2 chunks per thread
    const int bRow = tid >> 2;                 // 0..127
    const int bjb  = (tid & 3) << 1;           // 0,2,4,6
    const __half* gA = g_fp16 + (size_t)(m0 + aRow) * KL + (size_t)ajb * 8;
    const __half* gB = g_fp16 + NA + (size_t)(n0 + bRow) * KL + (size_t)bjb * 8;
    const u32 sRowA = (u32)aRow * 128;
    const u32 sRowB = (u32)bRow * 128;
    u32 swzA[4], swzB[2];
    #pragma unroll
    for (int j2 = 0; j2 < 4; ++j2)
        swzA[j2] = (u32)(((ajb + j2) ^ (aRow & 7)) << 4);
    #pragma unroll
    for (int j2 = 0; j2 < 2; ++j2)
        swzB[j2] = (u32)(((bjb + j2) ^ (bRow & 7)) << 4);

    // ---- ldmatrix per-lane bases: warp grid 4(M) x 4(N), tile 64x32 ----
    const int wm = (w >> 2) << 6;              // 0,64,128,192
    const int wn = (w & 3) << 5;               // 0,32,64,96
    const u32 raA = (u32)(wm + (lane & 15)) * 128;
    const u32 raB = (u32)(wn + (lane & 15)) * 128 + R_B;
    const u32 khalf = (u32)(lane >> 4);
    const u32 l7    = (u32)(lane & 7);

    float c[4][4][4] = {};
    u32 ah[2][4][4], bh[2][2][4];

    auto issue = [&](int ic) {
        if (ic < NCHUNK) {
            const u32 sdst = sb + (u32)(ic & 3) * STAGE;
            const size_t kbase = (size_t)(ic >> 4) * ((size_t)NT * KL)
                               + (size_t)((ic & 15) << 6);
            const __half* pa = gA + kbase;
            const __half* pb = gB + kbase;
            #pragma unroll
            for (int j2 = 0; j2 < 4; ++j2)
                cp16(sdst + sRowA + swzA[j2], pa + j2 * 8);
            #pragma unroll
            for (int j2 = 0; j2 < 2; ++j2)
                cp16(sdst + R_B + sRowB + swzB[j2], pb + j2 * 8);
        }
        asm volatile("cp.async.commit_group;" ::: "memory");
    };

    auto ldsm_kk = [&](u32 base, int kk, int fb) {
        const u32 off = (((u32)(2 * kk) + khalf) ^ l7) << 4;
        const u32 pa = base + raA + off;
        const u32 pb = base + raB + off;
        #pragma unroll
        for (int t = 0; t < 4; ++t) ldsm4(pa + (u32)t * 2048, ah[fb][t]);
        #pragma unroll
        for (int t = 0; t < 2; ++t) ldsm4(pb + (u32)t * 2048, bh[fb][t]);
    };

    // ---- prologue: stage chunks 0..2 ----
    issue(0); issue(1); issue(2);

    #pragma unroll 1
    for (int ic = 0; ic < NCHUNK; ++ic) {
        const u32 base = sb + (u32)(ic & 3) * STAGE;

        // Own-group wait, then barrier: chunk-ic data visible to all warps
        // AND all warps done reading the buffer issue() below overwrites.
        asm volatile("cp.async.wait_group 2;" ::: "memory");
        __syncthreads();

        issue(ic + 3);

        ldsm_kk(base, 0, 0);
        #pragma unroll
        for (int kk = 0; kk < 4; ++kk) {
            const int fb = kk & 1;
            if (kk < 3) ldsm_kk(base, kk + 1, fb ^ 1);   // prefetch next block

            // mt -> j: same-accumulator dep distance = 16 MMAs
            #pragma unroll
            for (int mt = 0; mt < 4; ++mt) {
                #pragma unroll
                for (int j = 0; j < 4; ++j) {
                    const int t = j >> 1, s = j & 1;
                    mma16816(c[mt][j], ah[fb][mt], bh[fb][t][s], bh[fb][t][s + 2]);
                }
            }
        }
    }

    // ---- epilogue ----
    const int orow = m0 + wm + (lane >> 2);
    const int ocol = n0 + wn + ((lane & 3) << 1);
    #pragma unroll
    for (int mt = 0; mt < 4; ++mt) {
        #pragma unroll
        for (int j = 0; j < 4; ++j) {
            float* p = out + (size_t)(orow + mt * 16) * NT + (ocol + j * 8);
            *reinterpret_cast<float2*>(p) = make_float2(c[mt][j][0], c[mt][j][1]);
            *reinterpret_cast<float2*>(p + (size_t)8 * NT) =
                make_float2(c[mt][j][2], c[mt][j][3]);
        }
    }
}

extern "C" void kernel_launch(void* const* d_in, const int* in_sizes, int n_in,
                              void* d_out, int out_size)
{
    const float* A = (const float*)d_in[0];   // [8, 4096, 1024]
    const float* W = (const float*)d_in[1];   // [8, 4096, 1024]
    float* out = (float*)d_out;               // [8, 512, 4096] == [4096, 4096]

    cvt_kernel<<<4096, 256>>>(A, W);

    cudaFuncSetAttribute(gemm_rs_kernel,
                         cudaFuncAttributeMaxDynamicSharedMemorySize, SMEM_TOTAL);
    gemm_rs_kernel<<<512, 512, SMEM_TOTAL>>>(out);
}

// round 14
// speedup vs baseline: 1.5284x; 1.0874x over previous
#include <cuda_runtime.h>
#include <cuda_fp16.h>

// ---------------------------------------------------------------------------
// out[m,n] = sum_r sum_k A[r,m,k] * W[r,n,k]   (M=N=4096, K=8*1024)
// fp32 in/out, fp16 single-pass mma.sync.m16n8k16 (f32 accumulate).
// R14: R13's inner loop (CTA 256x128, 16 warps of 64x32, 4-stage cp.async.cg
// ring) + split-K=2 to kill the 13.5% wave-quantization tail:
// grid 1024 = 512 tiles x 2 K-halves, epilogue atomicAdd into pre-zeroed out.
// ---------------------------------------------------------------------------

using u32 = unsigned int;

static constexpr int NT      = 4096;       // N total (also M total)
static constexpr int KL      = 1024;       // K per rank slab
static constexpr int NCH_H   = 64;         // chunks per split (half of 128)
static constexpr int R_B     = 32768;      // B region offset within a stage
static constexpr int STAGE   = 49152;      // A 32KB + B 16KB (fp16)
static constexpr int NSTG    = 4;
static constexpr int SMEM_TOTAL = NSTG * STAGE;          // 192 KB
static constexpr size_t NA   = (size_t)8 * NT * KL;      // elems per tensor

// fp16 scratch: A at [0, NA), W at [NA, 2*NA)  (128 MB)
__device__ __half g_fp16[2 * NA];

// ---------------- convert pass ----------------
__global__ __launch_bounds__(256) void cvt_kernel(const float* __restrict__ A,
                                                  const float* __restrict__ W)
{
    const size_t total8 = (2 * NA) / 8;
    const size_t stride = (size_t)gridDim.x * blockDim.x;
    for (size_t g = (size_t)blockIdx.x * blockDim.x + threadIdx.x;
         g < total8; g += stride) {
        const size_t off = g * 8;
        const float* src = (off < NA) ? (A + off) : (W + (off - NA));
        const float4 v0 = *reinterpret_cast<const float4*>(src);
        const float4 v1 = *reinterpret_cast<const float4*>(src + 4);
        const __half2 h0 = __floats2half2_rn(v0.x, v0.y);
        const __half2 h1 = __floats2half2_rn(v0.z, v0.w);
        const __half2 h2 = __floats2half2_rn(v1.x, v1.y);
        const __half2 h3 = __floats2half2_rn(v1.z, v1.w);
        uint4 pk;
        pk.x = *(const u32*)&h0; pk.y = *(const u32*)&h1;
        pk.z = *(const u32*)&h2; pk.w = *(const u32*)&h3;
        *reinterpret_cast<uint4*>(&g_fp16[off]) = pk;
    }
}

// ---------------- zero the output (harness poisons it) ----------------
__global__ __launch_bounds__(256) void zero_kernel(float4* __restrict__ out4)
{
    const size_t total = (size_t)NT * NT / 4;
    const size_t stride = (size_t)gridDim.x * blockDim.x;
    for (size_t g = (size_t)blockIdx.x * blockDim.x + threadIdx.x;
         g < total; g += stride)
        out4[g] = make_float4(0.f, 0.f, 0.f, 0.f);
}

// ---------------- GEMM ----------------
static __device__ __forceinline__ u32 smem_u32(const void* p) {
    u32 a;
    asm("{ .reg .u64 t; cvta.to.shared.u64 t, %1; cvt.u32.u64 %0, t; }"
        : "=r"(a) : "l"(p));
    return a;
}

static __device__ __forceinline__ void ldsm4(u32 addr, u32* r) {
    asm volatile("ldmatrix.sync.aligned.m8n8.x4.shared.b16 {%0,%1,%2,%3}, [%4];"
                 : "=r"(r[0]), "=r"(r[1]), "=r"(r[2]), "=r"(r[3]) : "r"(addr));
}

static __device__ __forceinline__ void mma16816(float* c, const u32* a,
                                                u32 b0, u32 b1) {
    asm volatile(
        "mma.sync.aligned.m16n8k16.row.col.f32.f16.f16.f32 "
        "{%0,%1,%2,%3}, {%4,%5,%6,%7}, {%8,%9}, {%0,%1,%2,%3};"
        : "+f"(c[0]), "+f"(c[1]), "+f"(c[2]), "+f"(c[3])
        : "r"(a[0]), "r"(a[1]), "r"(a[2]), "r"(a[3]), "r"(b0), "r"(b1));
}

static __device__ __forceinline__ void cp16(u32 sdst, const void* gsrc) {
    asm volatile("cp.async.cg.shared.global [%0], [%1], 16;"
                 :: "r"(sdst), "l"(gsrc) : "memory");
}

__global__ __launch_bounds__(512, 1)
void gemm_rs_kernel(float* __restrict__ out)
{
    extern __shared__ char smem[];
    const u32 sb  = smem_u32(smem);
    const int tid = threadIdx.x;
    const int lane = tid & 31;
    const int w    = tid >> 5;

    // Grid: 1024 = 512 tiles x 2 K-splits. Tile raster identical to R13:
    // groups of 8 M-tiles x 32 N-tiles (wave working set ~70MB < L2).
    const int lin   = blockIdx.x & 511;
    const int split = blockIdx.x >> 9;         // 0 or 1
    const int grp = lin >> 8;                  // 0..1
    const int rem = lin & 255;
    const int m0  = ((grp << 3) + (rem & 7)) << 8;   // * 256
    const int n0  = (rem >> 3) << 7;                 // * 128
    const int ic0 = split * NCH_H;             // global chunk base

    // ---- cp.async thread maps ----
    const int aRow = tid >> 1;                 // 0..255
    const int ajb  = (tid & 1) << 2;           // 0 or 4
    const int bRow = tid >> 2;                 // 0..127
    const int bjb  = (tid & 3) << 1;           // 0,2,4,6
    const __half* gA = g_fp16 + (size_t)(m0 + aRow) * KL + (size_t)ajb * 8;
    const __half* gB = g_fp16 + NA + (size_t)(n0 + bRow) * KL + (size_t)bjb * 8;
    const u32 sRowA = (u32)aRow * 128;
    const u32 sRowB = (u32)bRow * 128;
    u32 swzA[4], swzB[2];
    #pragma unroll
    for (int j2 = 0; j2 < 4; ++j2)
        swzA[j2] = (u32)(((ajb + j2) ^ (aRow & 7)) << 4);
    #pragma unroll
    for (int j2 = 0; j2 < 2; ++j2)
        swzB[j2] = (u32)(((bjb + j2) ^ (bRow & 7)) << 4);

    // ---- ldmatrix per-lane bases: warp grid 4(M) x 4(N), tile 64x32 ----
    const int wm = (w >> 2) << 6;              // 0,64,128,192
    const int wn = (w & 3) << 5;               // 0,32,64,96
    const u32 raA = (u32)(wm + (lane & 15)) * 128;
    const u32 raB = (u32)(wn + (lane & 15)) * 128 + R_B;
    const u32 khalf = (u32)(lane >> 4);
    const u32 l7    = (u32)(lane & 7);

    float c[4][4][4] = {};
    u32 ah[2][4][4], bh[2][2][4];

    // ic is the LOCAL chunk index within this split (0..63).
    auto issue = [&](int ic) {
        if (ic < NCH_H) {
            const int icg = ic0 + ic;          // global chunk
            const u32 sdst = sb + (u32)(ic & 3) * STAGE;
            const size_t kbase = (size_t)(icg >> 4) * ((size_t)NT * KL)
                               + (size_t)((icg & 15) << 6);
            const __half* pa = gA + kbase;
            const __half* pb = gB + kbase;
            #pragma unroll
            for (int j2 = 0; j2 < 4; ++j2)
                cp16(sdst + sRowA + swzA[j2], pa + j2 * 8);
            #pragma unroll
            for (int j2 = 0; j2 < 2; ++j2)
                cp16(sdst + R_B + sRowB + swzB[j2], pb + j2 * 8);
        }
        asm volatile("cp.async.commit_group;" ::: "memory");
    };

    auto ldsm_kk = [&](u32 base, int kk, int fb) {
        const u32 off = (((u32)(2 * kk) + khalf) ^ l7) << 4;
        const u32 pa = base + raA + off;
        const u32 pb = base + raB + off;
        #pragma unroll
        for (int t = 0; t < 4; ++t) ldsm4(pa + (u32)t * 2048, ah[fb][t]);
        #pragma unroll
        for (int t = 0; t < 2; ++t) ldsm4(pb + (u32)t * 2048, bh[fb][t]);
    };

    // ---- prologue: stage chunks 0..2 of this split ----
    issue(0); issue(1); issue(2);

    #pragma unroll 1
    for (int ic = 0; ic < NCH_H; ++ic) {
        const u32 base = sb + (u32)(ic & 3) * STAGE;

        // Own-group wait, then barrier: chunk-ic data visible to all warps
        // AND all warps done reading the buffer issue() below overwrites.
        asm volatile("cp.async.wait_group 2;" ::: "memory");
        __syncthreads();

        issue(ic + 3);

        ldsm_kk(base, 0, 0);
        #pragma unroll
        for (int kk = 0; kk < 4; ++kk) {
            const int fb = kk & 1;
            if (kk < 3) ldsm_kk(base, kk + 1, fb ^ 1);   // prefetch next block

            // mt -> j: same-accumulator dep distance = 16 MMAs
            #pragma unroll
            for (int mt = 0; mt < 4; ++mt) {
                #pragma unroll
                for (int j = 0; j < 4; ++j) {
                    const int t = j >> 1, s = j & 1;
                    mma16816(c[mt][j], ah[fb][mt], bh[fb][t][s], bh[fb][t][s + 2]);
                }
            }
        }
    }

    // ---- epilogue: atomic accumulate (two split contributors per tile) ----
    const int orow = m0 + wm + (lane >> 2);
    const int ocol = n0 + wn + ((lane & 3) << 1);
    #pragma unroll
    for (int mt = 0; mt < 4; ++mt) {
        #pragma unroll
        for (int j = 0; j < 4; ++j) {
            float* p = out + (size_t)(orow + mt * 16) * NT + (ocol + j * 8);
            atomicAdd(p,     c[mt][j][0]);
            atomicAdd(p + 1, c[mt][j][1]);
            atomicAdd(p + (size_t)8 * NT,     c[mt][j][2]);
            atomicAdd(p + (size_t)8 * NT + 1, c[mt][j][3]);
        }
    }
}

extern "C" void kernel_launch(void* const* d_in, const int* in_sizes, int n_in,
                              void* d_out, int out_size)
{
    const float* A = (const float*)d_in[0];   // [8, 4096, 1024]
    const float* W = (const float*)d_in[1];   // [8, 4096, 1024]
    float* out = (float*)d_out;               // [8, 512, 4096] == [4096, 4096]

    cvt_kernel<<<4096, 256>>>(A, W);
    zero_kernel<<<2048, 256>>>((float4*)out);

    cudaFuncSetAttribute(gemm_rs_kernel,
                         cudaFuncAttributeMaxDynamicSharedMemorySize, SMEM_TOTAL);
    gemm_rs_kernel<<<1024, 512, SMEM_TOTAL>>>(out);
}